// round 4
// baseline (speedup 1.0000x reference)
#include <cuda_runtime.h>
#include <cstdint>

#define N_NODES 100000
#define N_EDGES 50000
#define NNZ     800000
#define C       256
#define C4      (C / 4)   // 64 float4 per row

// ---------------- scratch (__device__ globals: allowed) ----------------
__device__ int   d_cnt_e[N_EDGES];
__device__ int   d_cnt_n[N_NODES];
__device__ int   d_off_e[N_EDGES + 1];
__device__ int   d_off_n[N_NODES + 1];
__device__ int   d_memb_e[NNZ];                // node ids grouped by edge
__device__ int   d_memb_n[NNZ];                // edge ids grouped by node

// ---------------------------------------------------------------------------
// 1. zero counters
// ---------------------------------------------------------------------------
__global__ void zero_cnt_kernel() {
    int idx = blockIdx.x * blockDim.x + threadIdx.x;
    int stride = gridDim.x * blockDim.x;
    for (int i = idx; i < N_EDGES; i += stride) d_cnt_e[i] = 0;
    for (int i = idx; i < N_NODES; i += stride) d_cnt_n[i] = 0;
}

// ---------------------------------------------------------------------------
// 2. histogram of both index arrays
// ---------------------------------------------------------------------------
__global__ void hist_kernel(const int* __restrict__ node_idx,
                            const int* __restrict__ edge_idx) {
    int idx = blockIdx.x * blockDim.x + threadIdx.x;
    int stride = gridDim.x * blockDim.x;
    for (int i = idx; i < NNZ; i += stride) {
        atomicAdd(&d_cnt_e[edge_idx[i]], 1);
        atomicAdd(&d_cnt_n[node_idx[i]], 1);
    }
}

// ---------------------------------------------------------------------------
// 3. exclusive scan, VT=4 (int4) per thread. block 0 -> edges, block 1 -> nodes.
//    Both lengths are divisible by 4. Re-zeroes counts for the fill pass.
// ---------------------------------------------------------------------------
__global__ __launch_bounds__(1024)
void scan_two_kernel() {
    int* cnt;
    int* off;
    int  L;
    if (blockIdx.x == 0) { cnt = d_cnt_e; off = d_off_e; L = N_EDGES; }
    else                 { cnt = d_cnt_n; off = d_off_n; L = N_NODES; }

    const int tid  = threadIdx.x;
    const int lane = tid & 31;
    const int wid  = tid >> 5;
    __shared__ int warp_sum[32];

    const int L4 = L >> 2;                   // int4 count
    int running = 0;
    for (int base4 = 0; base4 < L4; base4 += 1024) {
        int i4 = base4 + tid;
        int4 v = make_int4(0, 0, 0, 0);
        if (i4 < L4) v = reinterpret_cast<const int4*>(cnt)[i4];
        // local inclusive prefix
        int p0 = v.x;
        int p1 = p0 + v.y;
        int p2 = p1 + v.z;
        int p3 = p2 + v.w;
        int tot = p3;
        // warp inclusive scan of totals
        int w = tot;
        #pragma unroll
        for (int d = 1; d < 32; d <<= 1) {
            int t = __shfl_up_sync(0xffffffffu, w, d);
            if (lane >= d) w += t;
        }
        if (lane == 31) warp_sum[wid] = w;
        __syncthreads();
        if (wid == 0) {
            int ws = warp_sum[lane];
            #pragma unroll
            for (int d = 1; d < 32; d <<= 1) {
                int t = __shfl_up_sync(0xffffffffu, ws, d);
                if (lane >= d) ws += t;
            }
            warp_sum[lane] = ws;
        }
        __syncthreads();
        int excl = (w - tot) + (wid > 0 ? warp_sum[wid - 1] : 0) + running;
        if (i4 < L4) {
            int i = i4 * 4;
            off[i + 1] = excl + p0;
            off[i + 2] = excl + p1;
            off[i + 3] = excl + p2;
            off[i + 4] = excl + p3;
        }
        running += warp_sum[31];
        __syncthreads();
    }
    if (tid == 0) off[0] = 0;
    for (int i = tid; i < L; i += 1024) cnt[i] = 0;
}

// ---------------------------------------------------------------------------
// 4. fill member lists (rank via int atomics)
// ---------------------------------------------------------------------------
__global__ void fill_kernel(const int* __restrict__ node_idx,
                            const int* __restrict__ edge_idx) {
    int idx = blockIdx.x * blockDim.x + threadIdx.x;
    int stride = gridDim.x * blockDim.x;
    for (int i = idx; i < NNZ; i += stride) {
        int n = node_idx[i];
        int e = edge_idx[i];
        int re = atomicAdd(&d_cnt_e[e], 1);
        d_memb_e[d_off_e[e] + re] = n;
        int rn = atomicAdd(&d_cnt_n[n], 1);
        d_memb_n[d_off_n[n] + rn] = e;
    }
}

// ---------------------------------------------------------------------------
// 5. reduce v2e: x1[e] = sum over member nodes of x0[n]   (no atomics)
// ---------------------------------------------------------------------------
__global__ __launch_bounds__(64)
void reduce_v2e(const float4* __restrict__ x0, float4* __restrict__ x1) {
    const int e   = blockIdx.x;
    const int tid = threadIdx.x;
    int beg = d_off_e[e];
    int end = d_off_e[e + 1];

    float4 s0 = make_float4(0.f, 0.f, 0.f, 0.f);
    float4 s1 = make_float4(0.f, 0.f, 0.f, 0.f);
    int j = beg;
    for (; j + 1 < end; j += 2) {
        int n0 = __ldg(&d_memb_e[j]);
        int n1 = __ldg(&d_memb_e[j + 1]);
        float4 v0 = __ldg(&x0[(size_t)n0 * C4 + tid]);
        float4 v1 = __ldg(&x0[(size_t)n1 * C4 + tid]);
        s0.x += v0.x; s0.y += v0.y; s0.z += v0.z; s0.w += v0.w;
        s1.x += v1.x; s1.y += v1.y; s1.z += v1.z; s1.w += v1.w;
    }
    if (j < end) {
        int n0 = __ldg(&d_memb_e[j]);
        float4 v0 = __ldg(&x0[(size_t)n0 * C4 + tid]);
        s0.x += v0.x; s0.y += v0.y; s0.z += v0.z; s0.w += v0.w;
    }
    s0.x += s1.x; s0.y += s1.y; s0.z += s1.z; s0.w += s1.w;
    x1[(size_t)e * C4 + tid] = s0;
}

// ---------------------------------------------------------------------------
// 6. FUSED: out0 = (x0 + sum_{e in N(n)} x1[e]) @ W^T + b
//    Prologue builds the 64x256 A panel (tf32) in smem by segment reduction,
//    then TF32 mma.sync mainloop stages only W tiles.
// ---------------------------------------------------------------------------
#define GBM 64
#define GBK 16
#define ASTRIDE 260   // words per A row (pad 4); 260%4==0 for uint4, 260%32==4 for banks
#define BPAD 20       // W tile row stride (words)

#define SMEM_WORDS (GBM * ASTRIDE + 256 * BPAD)

__device__ __forceinline__ uint32_t f2tf32(float f) {
    uint32_t r;
    asm("cvt.rna.tf32.f32 %0, %1;" : "=r"(r) : "f"(f));
    return r;
}

__device__ __forceinline__ void mma_tf32(float c[4], const uint32_t a[4], const uint32_t b[2]) {
    asm volatile(
        "mma.sync.aligned.m16n8k8.row.col.f32.tf32.tf32.f32 "
        "{%0,%1,%2,%3}, {%4,%5,%6,%7}, {%8,%9}, {%0,%1,%2,%3};\n"
        : "+f"(c[0]), "+f"(c[1]), "+f"(c[2]), "+f"(c[3])
        : "r"(a[0]), "r"(a[1]), "r"(a[2]), "r"(a[3]), "r"(b[0]), "r"(b[1]));
}

__global__ __launch_bounds__(256)
void gin_fused_gemm(const float4* __restrict__ x0,
                    const float4* __restrict__ x1,
                    const float* __restrict__ W,
                    const float* __restrict__ bias,
                    float* __restrict__ out) {
    extern __shared__ uint32_t smem[];
    uint32_t* As = smem;                       // [GBM][ASTRIDE] tf32, full K=256
    uint32_t* Bs = smem + GBM * ASTRIDE;       // [256][BPAD] tf32, one k-tile

    const int tid  = threadIdx.x;
    const int lane = tid & 31;
    const int wid  = tid >> 5;
    const int m0 = blockIdx.x * GBM;

    // ---------------- prologue: build A panel ----------------
    {
        const int c4      = tid & 63;          // float4 channel group 0..63
        const int row_grp = tid >> 6;          // 0..3, each handles 16 rows
        #pragma unroll 1
        for (int rr = 0; rr < 16; rr++) {
            int row = row_grp * 16 + rr;
            int n = m0 + row;
            float4 s0 = make_float4(0.f, 0.f, 0.f, 0.f);
            if (n < N_NODES) {
                s0 = __ldg(&x0[(size_t)n * C4 + c4]);
                int beg = __ldg(&d_off_n[n]);
                int end = __ldg(&d_off_n[n + 1]);
                float4 s1 = make_float4(0.f, 0.f, 0.f, 0.f);
                int j = beg;
                for (; j + 1 < end; j += 2) {
                    int e0 = __ldg(&d_memb_n[j]);
                    int e1 = __ldg(&d_memb_n[j + 1]);
                    float4 v0 = __ldg(&x1[(size_t)e0 * C4 + c4]);
                    float4 v1 = __ldg(&x1[(size_t)e1 * C4 + c4]);
                    s0.x += v0.x; s0.y += v0.y; s0.z += v0.z; s0.w += v0.w;
                    s1.x += v1.x; s1.y += v1.y; s1.z += v1.z; s1.w += v1.w;
                }
                if (j < end) {
                    int e0 = __ldg(&d_memb_n[j]);
                    float4 v0 = __ldg(&x1[(size_t)e0 * C4 + c4]);
                    s0.x += v0.x; s0.y += v0.y; s0.z += v0.z; s0.w += v0.w;
                }
                s0.x += s1.x; s0.y += s1.y; s0.z += s1.z; s0.w += s1.w;
            }
            uint4 t;
            t.x = f2tf32(s0.x); t.y = f2tf32(s0.y);
            t.z = f2tf32(s0.z); t.w = f2tf32(s0.w);
            *reinterpret_cast<uint4*>(&As[row * ASTRIDE + c4 * 4]) = t;
        }
    }

    // ---------------- GEMM mainloop ----------------
    const int m_off = (wid >> 2) * 32;         // 0 or 32
    const int n_off = (wid & 3) * 64;          // 0,64,128,192
    const int r  = lane >> 2;                  // 0..7
    const int cq = lane & 3;                   // 0..3

    // B load mapping: rows tid>>1 and +128, cols (tid&1)*8..+7
    const int b_row = tid >> 1;
    const int b_col = (tid & 1) * 8;
    const size_t b_base = (size_t)b_row * C + b_col;

    float acc[2][8][4];
    #pragma unroll
    for (int mf = 0; mf < 2; mf++)
        #pragma unroll
        for (int nf = 0; nf < 8; nf++)
            #pragma unroll
            for (int q = 0; q < 4; q++)
                acc[mf][nf][q] = 0.f;

    // prefetch W tile 0
    float4 pb0 = *reinterpret_cast<const float4*>(&W[b_base + 0]);
    float4 pb1 = *reinterpret_cast<const float4*>(&W[b_base + 4]);
    float4 pb2 = *reinterpret_cast<const float4*>(&W[b_base + (size_t)128 * C + 0]);
    float4 pb3 = *reinterpret_cast<const float4*>(&W[b_base + (size_t)128 * C + 4]);

    __syncthreads();   // A panel ready (covers prologue too)

    for (int t = 0; t < C / GBK; t++) {
        // stage W tile
        Bs[b_row * BPAD + b_col + 0] = f2tf32(pb0.x);
        Bs[b_row * BPAD + b_col + 1] = f2tf32(pb0.y);
        Bs[b_row * BPAD + b_col + 2] = f2tf32(pb0.z);
        Bs[b_row * BPAD + b_col + 3] = f2tf32(pb0.w);
        Bs[b_row * BPAD + b_col + 4] = f2tf32(pb1.x);
        Bs[b_row * BPAD + b_col + 5] = f2tf32(pb1.y);
        Bs[b_row * BPAD + b_col + 6] = f2tf32(pb1.z);
        Bs[b_row * BPAD + b_col + 7] = f2tf32(pb1.w);
        Bs[(b_row + 128) * BPAD + b_col + 0] = f2tf32(pb2.x);
        Bs[(b_row + 128) * BPAD + b_col + 1] = f2tf32(pb2.y);
        Bs[(b_row + 128) * BPAD + b_col + 2] = f2tf32(pb2.z);
        Bs[(b_row + 128) * BPAD + b_col + 3] = f2tf32(pb2.w);
        Bs[(b_row + 128) * BPAD + b_col + 4] = f2tf32(pb3.x);
        Bs[(b_row + 128) * BPAD + b_col + 5] = f2tf32(pb3.y);
        Bs[(b_row + 128) * BPAD + b_col + 6] = f2tf32(pb3.z);
        Bs[(b_row + 128) * BPAD + b_col + 7] = f2tf32(pb3.w);
        __syncthreads();

        // prefetch next W tile
        if (t + 1 < C / GBK) {
            int k0 = (t + 1) * GBK;
            pb0 = *reinterpret_cast<const float4*>(&W[b_base + k0 + 0]);
            pb1 = *reinterpret_cast<const float4*>(&W[b_base + k0 + 4]);
            pb2 = *reinterpret_cast<const float4*>(&W[b_base + (size_t)128 * C + k0 + 0]);
            pb3 = *reinterpret_cast<const float4*>(&W[b_base + (size_t)128 * C + k0 + 4]);
        }

        #pragma unroll
        for (int ks = 0; ks < 2; ks++) {
            const int kA = t * GBK + ks * 8;   // k offset into A panel
            const int kB = ks * 8;             // k offset into staged B tile
            uint32_t aF[2][4];
            #pragma unroll
            for (int mf = 0; mf < 2; mf++) {
                int row = m_off + mf * 16 + r;
                aF[mf][0] = As[row * ASTRIDE + kA + cq];
                aF[mf][1] = As[(row + 8) * ASTRIDE + kA + cq];
                aF[mf][2] = As[row * ASTRIDE + kA + cq + 4];
                aF[mf][3] = As[(row + 8) * ASTRIDE + kA + cq + 4];
            }
            #pragma unroll
            for (int nf = 0; nf < 8; nf++) {
                uint32_t bF[2];
                int col = n_off + nf * 8 + r;
                bF[0] = Bs[col * BPAD + kB + cq];
                bF[1] = Bs[col * BPAD + kB + cq + 4];
                mma_tf32(acc[0][nf], aF[0], bF);
                mma_tf32(acc[1][nf], aF[1], bF);
            }
        }
        __syncthreads();
    }

    // ---------------- epilogue ----------------
    #pragma unroll
    for (int mf = 0; mf < 2; mf++) {
        #pragma unroll
        for (int nf = 0; nf < 8; nf++) {
            int gc = n_off + nf * 8 + cq * 2;
            float bb0 = bias[gc];
            float bb1 = bias[gc + 1];
            int gr = m0 + m_off + mf * 16 + r;
            if (gr < N_NODES) {
                float2 v = make_float2(acc[mf][nf][0] + bb0, acc[mf][nf][1] + bb1);
                *reinterpret_cast<float2*>(&out[(size_t)gr * C + gc]) = v;
            }
            if (gr + 8 < N_NODES) {
                float2 v = make_float2(acc[mf][nf][2] + bb0, acc[mf][nf][3] + bb1);
                *reinterpret_cast<float2*>(&out[(size_t)(gr + 8) * C + gc]) = v;
            }
        }
    }
}

// ---------------------------------------------------------------------------
// Launch
// ---------------------------------------------------------------------------
extern "C" void kernel_launch(void* const* d_in, const int* in_sizes, int n_in,
                              void* d_out, int out_size) {
    const float* x0       = (const float*)d_in[0];
    const int*   node_idx = (const int*)d_in[1];
    const int*   edge_idx = (const int*)d_in[2];
    const float* W        = (const float*)d_in[3];
    const float* b        = (const float*)d_in[4];

    float* out = (float*)d_out;
    float* x1  = out + (size_t)N_NODES * C;

    // CSR build
    zero_cnt_kernel<<<256, 256>>>();
    hist_kernel<<<800, 256>>>(node_idx, edge_idx);
    scan_two_kernel<<<2, 1024>>>();
    fill_kernel<<<800, 256>>>(node_idx, edge_idx);

    // segment reduction v2e (x1 is part of the output)
    reduce_v2e<<<N_EDGES, 64>>>(reinterpret_cast<const float4*>(x0),
                                reinterpret_cast<float4*>(x1));

    // fused e2v reduction + GEMM
    {
        const int smem_bytes = SMEM_WORDS * 4;   // ~87 KB
        cudaFuncSetAttribute(gin_fused_gemm,
                             cudaFuncAttributeMaxDynamicSharedMemorySize,
                             smem_bytes);
        int grid = (N_NODES + GBM - 1) / GBM;    // 1563
        gin_fused_gemm<<<grid, 256, smem_bytes>>>(
            reinterpret_cast<const float4*>(x0),
            reinterpret_cast<const float4*>(x1),
            W, b, out);
    }
}

// round 6
// speedup vs baseline: 1.3593x; 1.3593x over previous
#include <cuda_runtime.h>
#include <cstdint>

#define N_NODES 100000
#define N_EDGES 50000
#define NNZ     800000
#define C       256
#define C4      (C / 4)   // 64 float4 per row

// ---------------- scratch (__device__ globals: allowed) ----------------
__device__ float g_m[(size_t)N_NODES * C];     // fused (x0 + m) for GEMM A
__device__ int   d_cnt_e[N_EDGES];
__device__ int   d_cnt_n[N_NODES];
__device__ int   d_off_e[N_EDGES + 1];
__device__ int   d_off_n[N_NODES + 1];
__device__ int   d_memb_e[NNZ];                // node ids grouped by edge
__device__ int   d_memb_n[NNZ];                // edge ids grouped by node

// ---------------------------------------------------------------------------
// 1. zero counters
// ---------------------------------------------------------------------------
__global__ void zero_cnt_kernel() {
    int idx = blockIdx.x * blockDim.x + threadIdx.x;
    int stride = gridDim.x * blockDim.x;
    for (int i = idx; i < N_EDGES; i += stride) d_cnt_e[i] = 0;
    for (int i = idx; i < N_NODES; i += stride) d_cnt_n[i] = 0;
}

// ---------------------------------------------------------------------------
// 2. histogram of both index arrays
// ---------------------------------------------------------------------------
__global__ void hist_kernel(const int* __restrict__ node_idx,
                            const int* __restrict__ edge_idx) {
    int idx = blockIdx.x * blockDim.x + threadIdx.x;
    int stride = gridDim.x * blockDim.x;
    for (int i = idx; i < NNZ; i += stride) {
        atomicAdd(&d_cnt_e[edge_idx[i]], 1);
        atomicAdd(&d_cnt_n[node_idx[i]], 1);
    }
}

// ---------------------------------------------------------------------------
// 3. exclusive scan, VT=4 (int4) per thread. block 0 -> edges, block 1 -> nodes.
// ---------------------------------------------------------------------------
__global__ __launch_bounds__(1024)
void scan_two_kernel() {
    int* cnt;
    int* off;
    int  L;
    if (blockIdx.x == 0) { cnt = d_cnt_e; off = d_off_e; L = N_EDGES; }
    else                 { cnt = d_cnt_n; off = d_off_n; L = N_NODES; }

    const int tid  = threadIdx.x;
    const int lane = tid & 31;
    const int wid  = tid >> 5;
    __shared__ int warp_sum[32];

    const int L4 = L >> 2;
    int running = 0;
    for (int base4 = 0; base4 < L4; base4 += 1024) {
        int i4 = base4 + tid;
        int4 v = make_int4(0, 0, 0, 0);
        if (i4 < L4) v = reinterpret_cast<const int4*>(cnt)[i4];
        int p0 = v.x;
        int p1 = p0 + v.y;
        int p2 = p1 + v.z;
        int p3 = p2 + v.w;
        int tot = p3;
        int w = tot;
        #pragma unroll
        for (int d = 1; d < 32; d <<= 1) {
            int t = __shfl_up_sync(0xffffffffu, w, d);
            if (lane >= d) w += t;
        }
        if (lane == 31) warp_sum[wid] = w;
        __syncthreads();
        if (wid == 0) {
            int ws = warp_sum[lane];
            #pragma unroll
            for (int d = 1; d < 32; d <<= 1) {
                int t = __shfl_up_sync(0xffffffffu, ws, d);
                if (lane >= d) ws += t;
            }
            warp_sum[lane] = ws;
        }
        __syncthreads();
        int excl = (w - tot) + (wid > 0 ? warp_sum[wid - 1] : 0) + running;
        if (i4 < L4) {
            int i = i4 * 4;
            off[i + 1] = excl + p0;
            off[i + 2] = excl + p1;
            off[i + 3] = excl + p2;
            off[i + 4] = excl + p3;
        }
        running += warp_sum[31];
        __syncthreads();
    }
    if (tid == 0) off[0] = 0;
    for (int i = tid; i < L; i += 1024) cnt[i] = 0;
}

// ---------------------------------------------------------------------------
// 4. fill member lists (rank via int atomics)
// ---------------------------------------------------------------------------
__global__ void fill_kernel(const int* __restrict__ node_idx,
                            const int* __restrict__ edge_idx) {
    int idx = blockIdx.x * blockDim.x + threadIdx.x;
    int stride = gridDim.x * blockDim.x;
    for (int i = idx; i < NNZ; i += stride) {
        int n = node_idx[i];
        int e = edge_idx[i];
        int re = atomicAdd(&d_cnt_e[e], 1);
        d_memb_e[d_off_e[e] + re] = n;
        int rn = atomicAdd(&d_cnt_n[n], 1);
        d_memb_n[d_off_n[n] + rn] = e;
    }
}

// ---------------------------------------------------------------------------
// 5. reduce v2e: x1[e] = sum over member nodes of x0[n]
// ---------------------------------------------------------------------------
__global__ __launch_bounds__(64)
void reduce_v2e(const float4* __restrict__ x0, float4* __restrict__ x1) {
    const int e   = blockIdx.x;
    const int tid = threadIdx.x;
    int beg = d_off_e[e];
    int end = d_off_e[e + 1];

    float4 s0 = make_float4(0.f, 0.f, 0.f, 0.f);
    float4 s1 = make_float4(0.f, 0.f, 0.f, 0.f);
    int j = beg;
    for (; j + 1 < end; j += 2) {
        int n0 = __ldg(&d_memb_e[j]);
        int n1 = __ldg(&d_memb_e[j + 1]);
        float4 v0 = __ldg(&x0[(size_t)n0 * C4 + tid]);
        float4 v1 = __ldg(&x0[(size_t)n1 * C4 + tid]);
        s0.x += v0.x; s0.y += v0.y; s0.z += v0.z; s0.w += v0.w;
        s1.x += v1.x; s1.y += v1.y; s1.z += v1.z; s1.w += v1.w;
    }
    if (j < end) {
        int n0 = __ldg(&d_memb_e[j]);
        float4 v0 = __ldg(&x0[(size_t)n0 * C4 + tid]);
        s0.x += v0.x; s0.y += v0.y; s0.z += v0.z; s0.w += v0.w;
    }
    s0.x += s1.x; s0.y += s1.y; s0.z += s1.z; s0.w += s1.w;
    x1[(size_t)e * C4 + tid] = s0;
}

// ---------------------------------------------------------------------------
// 6. reduce e2v (fused with +x0): g_m[n] = x0[n] + sum incident x1[e]
// ---------------------------------------------------------------------------
__global__ __launch_bounds__(64)
void reduce_e2v(const float4* __restrict__ x0, const float4* __restrict__ x1) {
    const int n   = blockIdx.x;
    const int tid = threadIdx.x;
    int beg = d_off_n[n];
    int end = d_off_n[n + 1];

    float4 s0 = __ldg(&x0[(size_t)n * C4 + tid]);
    float4 s1 = make_float4(0.f, 0.f, 0.f, 0.f);
    int j = beg;
    for (; j + 1 < end; j += 2) {
        int e0 = __ldg(&d_memb_n[j]);
        int e1 = __ldg(&d_memb_n[j + 1]);
        float4 v0 = __ldg(&x1[(size_t)e0 * C4 + tid]);
        float4 v1 = __ldg(&x1[(size_t)e1 * C4 + tid]);
        s0.x += v0.x; s0.y += v0.y; s0.z += v0.z; s0.w += v0.w;
        s1.x += v1.x; s1.y += v1.y; s1.z += v1.z; s1.w += v1.w;
    }
    if (j < end) {
        int e0 = __ldg(&d_memb_n[j]);
        float4 v0 = __ldg(&x1[(size_t)e0 * C4 + tid]);
        s0.x += v0.x; s0.y += v0.y; s0.z += v0.z; s0.w += v0.w;
    }
    s0.x += s1.x; s0.y += s1.y; s0.z += s1.z; s0.w += s1.w;
    float4* m4 = reinterpret_cast<float4*>(g_m);
    m4[(size_t)n * C4 + tid] = s0;
}

// ---------------------------------------------------------------------------
// 7. GEMM: out0 = g_m @ W^T + b  — TF32 mma, BM=128 BN=256 GBK=16,
//    8 warps (2x4), warp tile 64x64, double-buffered smem, 1 sync/tile.
// ---------------------------------------------------------------------------
#define GBM 128
#define GBK 16
#define SPAD 20
#define NTILES (C / GBK)

__device__ __forceinline__ uint32_t f2tf32(float f) {
    uint32_t r;
    asm("cvt.rna.tf32.f32 %0, %1;" : "=r"(r) : "f"(f));
    return r;
}

__device__ __forceinline__ void mma_tf32_v(float c[4], const uint32_t a[4], const uint32_t b[2]) {
    asm volatile(
        "mma.sync.aligned.m16n8k8.row.col.f32.tf32.tf32.f32 "
        "{%0,%1,%2,%3}, {%4,%5,%6,%7}, {%8,%9}, {%0,%1,%2,%3};\n"
        : "+f"(c[0]), "+f"(c[1]), "+f"(c[2]), "+f"(c[3])
        : "r"(a[0]), "r"(a[1]), "r"(a[2]), "r"(a[3]), "r"(b[0]), "r"(b[1]));
}

__global__ __launch_bounds__(256, 1)
void gin_gemm_tf32(const float* __restrict__ W,
                   const float* __restrict__ bias,
                   float* __restrict__ out) {
    extern __shared__ uint32_t smem[];
    // As[2][GBM][SPAD], Bs[2][256][SPAD]
    uint32_t* As0 = smem;
    uint32_t* Bs0 = smem + 2 * GBM * SPAD;

    const int tid  = threadIdx.x;
    const int lane = tid & 31;
    const int wid  = tid >> 5;
    const int m_off = (wid >> 2) * 64;   // 0 or 64
    const int n_off = (wid & 3) * 64;    // 0,64,128,192
    const int m0 = blockIdx.x * GBM;

    // A load mapping: 128 rows x 2 float4 groups = 256 threads
    const int a_row = tid >> 1;                 // 0..127
    const int a_col = (tid & 1) * 8;            // 0 or 8
    const int  a_gm  = m0 + a_row;
    const bool a_ok  = a_gm < N_NODES;
    const size_t a_base = (size_t)a_gm * C + a_col;

    // B load mapping: rows tid>>1 and +128, cols (tid&1)*8..+7
    const int b_row = tid >> 1;
    const int b_col = (tid & 1) * 8;
    const size_t b_base = (size_t)b_row * C + b_col;

    float acc[4][8][4];
    #pragma unroll
    for (int mf = 0; mf < 4; mf++)
        #pragma unroll
        for (int nf = 0; nf < 8; nf++)
            #pragma unroll
            for (int q = 0; q < 4; q++)
                acc[mf][nf][q] = 0.f;

    const int r  = lane >> 2;
    const int cq = lane & 3;

    // ---- load tile 0 directly into buffer 0 ----
    {
        float4 pa0 = make_float4(0.f,0.f,0.f,0.f), pa1 = pa0;
        if (a_ok) {
            pa0 = *reinterpret_cast<const float4*>(&g_m[a_base + 0]);
            pa1 = *reinterpret_cast<const float4*>(&g_m[a_base + 4]);
        }
        float4 pb0 = *reinterpret_cast<const float4*>(&W[b_base + 0]);
        float4 pb1 = *reinterpret_cast<const float4*>(&W[b_base + 4]);
        float4 pb2 = *reinterpret_cast<const float4*>(&W[b_base + (size_t)128 * C + 0]);
        float4 pb3 = *reinterpret_cast<const float4*>(&W[b_base + (size_t)128 * C + 4]);
        uint32_t* A = As0;
        uint32_t* B = Bs0;
        A[a_row * SPAD + a_col + 0] = f2tf32(pa0.x);
        A[a_row * SPAD + a_col + 1] = f2tf32(pa0.y);
        A[a_row * SPAD + a_col + 2] = f2tf32(pa0.z);
        A[a_row * SPAD + a_col + 3] = f2tf32(pa0.w);
        A[a_row * SPAD + a_col + 4] = f2tf32(pa1.x);
        A[a_row * SPAD + a_col + 5] = f2tf32(pa1.y);
        A[a_row * SPAD + a_col + 6] = f2tf32(pa1.z);
        A[a_row * SPAD + a_col + 7] = f2tf32(pa1.w);
        B[b_row * SPAD + b_col + 0] = f2tf32(pb0.x);
        B[b_row * SPAD + b_col + 1] = f2tf32(pb0.y);
        B[b_row * SPAD + b_col + 2] = f2tf32(pb0.z);
        B[b_row * SPAD + b_col + 3] = f2tf32(pb0.w);
        B[b_row * SPAD + b_col + 4] = f2tf32(pb1.x);
        B[b_row * SPAD + b_col + 5] = f2tf32(pb1.y);
        B[b_row * SPAD + b_col + 6] = f2tf32(pb1.z);
        B[b_row * SPAD + b_col + 7] = f2tf32(pb1.w);
        B[(b_row + 128) * SPAD + b_col + 0] = f2tf32(pb2.x);
        B[(b_row + 128) * SPAD + b_col + 1] = f2tf32(pb2.y);
        B[(b_row + 128) * SPAD + b_col + 2] = f2tf32(pb2.z);
        B[(b_row + 128) * SPAD + b_col + 3] = f2tf32(pb2.w);
        B[(b_row + 128) * SPAD + b_col + 4] = f2tf32(pb3.x);
        B[(b_row + 128) * SPAD + b_col + 5] = f2tf32(pb3.y);
        B[(b_row + 128) * SPAD + b_col + 6] = f2tf32(pb3.z);
        B[(b_row + 128) * SPAD + b_col + 7] = f2tf32(pb3.w);
    }
    __syncthreads();

    for (int t = 0; t < NTILES; t++) {
        const int buf = t & 1;
        uint32_t* A = As0 + buf * GBM * SPAD;
        uint32_t* B = Bs0 + buf * 256 * SPAD;

        // prefetch next tile into registers
        float4 pa0, pa1, pb0, pb1, pb2, pb3;
        const bool have_next = (t + 1 < NTILES);
        if (have_next) {
            int k0 = (t + 1) * GBK;
            if (a_ok) {
                pa0 = *reinterpret_cast<const float4*>(&g_m[a_base + k0 + 0]);
                pa1 = *reinterpret_cast<const float4*>(&g_m[a_base + k0 + 4]);
            } else { pa0 = make_float4(0.f,0.f,0.f,0.f); pa1 = pa0; }
            pb0 = *reinterpret_cast<const float4*>(&W[b_base + k0 + 0]);
            pb1 = *reinterpret_cast<const float4*>(&W[b_base + k0 + 4]);
            pb2 = *reinterpret_cast<const float4*>(&W[b_base + (size_t)128 * C + k0 + 0]);
            pb3 = *reinterpret_cast<const float4*>(&W[b_base + (size_t)128 * C + k0 + 4]);
        }

        // compute on current buffer: 2 ksteps
        #pragma unroll
        for (int ks = 0; ks < 2; ks++) {
            const int kk = ks * 8;
            uint32_t aF[4][4];
            #pragma unroll
            for (int mf = 0; mf < 4; mf++) {
                int row = m_off + mf * 16 + r;
                aF[mf][0] = A[row * SPAD + kk + cq];
                aF[mf][1] = A[(row + 8) * SPAD + kk + cq];
                aF[mf][2] = A[row * SPAD + kk + cq + 4];
                aF[mf][3] = A[(row + 8) * SPAD + kk + cq + 4];
            }
            #pragma unroll
            for (int nf = 0; nf < 8; nf++) {
                uint32_t bF[2];
                int col = n_off + nf * 8 + r;
                bF[0] = B[col * SPAD + kk + cq];
                bF[1] = B[col * SPAD + kk + cq + 4];
                #pragma unroll
                for (int mf = 0; mf < 4; mf++)
                    mma_tf32_v(acc[mf][nf], aF[mf], bF);
            }
        }

        // stage prefetched tile into the other buffer
        if (have_next) {
            uint32_t* An = As0 + (buf ^ 1) * GBM * SPAD;
            uint32_t* Bn = Bs0 + (buf ^ 1) * 256 * SPAD;
            An[a_row * SPAD + a_col + 0] = f2tf32(pa0.x);
            An[a_row * SPAD + a_col + 1] = f2tf32(pa0.y);
            An[a_row * SPAD + a_col + 2] = f2tf32(pa0.z);
            An[a_row * SPAD + a_col + 3] = f2tf32(pa0.w);
            An[a_row * SPAD + a_col + 4] = f2tf32(pa1.x);
            An[a_row * SPAD + a_col + 5] = f2tf32(pa1.y);
            An[a_row * SPAD + a_col + 6] = f2tf32(pa1.z);
            An[a_row * SPAD + a_col + 7] = f2tf32(pa1.w);
            Bn[b_row * SPAD + b_col + 0] = f2tf32(pb0.x);
            Bn[b_row * SPAD + b_col + 1] = f2tf32(pb0.y);
            Bn[b_row * SPAD + b_col + 2] = f2tf32(pb0.z);
            Bn[b_row * SPAD + b_col + 3] = f2tf32(pb0.w);
            Bn[b_row * SPAD + b_col + 4] = f2tf32(pb1.x);
            Bn[b_row * SPAD + b_col + 5] = f2tf32(pb1.y);
            Bn[b_row * SPAD + b_col + 6] = f2tf32(pb1.z);
            Bn[b_row * SPAD + b_col + 7] = f2tf32(pb1.w);
            Bn[(b_row + 128) * SPAD + b_col + 0] = f2tf32(pb2.x);
            Bn[(b_row + 128) * SPAD + b_col + 1] = f2tf32(pb2.y);
            Bn[(b_row + 128) * SPAD + b_col + 2] = f2tf32(pb2.z);
            Bn[(b_row + 128) * SPAD + b_col + 3] = f2tf32(pb2.w);
            Bn[(b_row + 128) * SPAD + b_col + 4] = f2tf32(pb3.x);
            Bn[(b_row + 128) * SPAD + b_col + 5] = f2tf32(pb3.y);
            Bn[(b_row + 128) * SPAD + b_col + 6] = f2tf32(pb3.z);
            Bn[(b_row + 128) * SPAD + b_col + 7] = f2tf32(pb3.w);
            __syncthreads();
        }
    }

    // ---- epilogue ----
    #pragma unroll
    for (int mf = 0; mf < 4; mf++) {
        #pragma unroll
        for (int nf = 0; nf < 8; nf++) {
            int gc = n_off + nf * 8 + cq * 2;
            float bb0 = bias[gc];
            float bb1 = bias[gc + 1];
            int gr = m0 + m_off + mf * 16 + r;
            if (gr < N_NODES) {
                float2 v = make_float2(acc[mf][nf][0] + bb0, acc[mf][nf][1] + bb1);
                *reinterpret_cast<float2*>(&out[(size_t)gr * C + gc]) = v;
            }
            if (gr + 8 < N_NODES) {
                float2 v = make_float2(acc[mf][nf][2] + bb0, acc[mf][nf][3] + bb1);
                *reinterpret_cast<float2*>(&out[(size_t)(gr + 8) * C + gc]) = v;
            }
        }
    }
}

#define GEMM_SMEM_BYTES ((2 * GBM * SPAD + 2 * 256 * SPAD) * 4)

// ---------------------------------------------------------------------------
// Launch
// ---------------------------------------------------------------------------
extern "C" void kernel_launch(void* const* d_in, const int* in_sizes, int n_in,
                              void* d_out, int out_size) {
    const float* x0       = (const float*)d_in[0];
    const int*   node_idx = (const int*)d_in[1];
    const int*   edge_idx = (const int*)d_in[2];
    const float* W        = (const float*)d_in[3];
    const float* b        = (const float*)d_in[4];

    float* out = (float*)d_out;
    float* x1  = out + (size_t)N_NODES * C;

    // CSR build
    zero_cnt_kernel<<<256, 256>>>();
    hist_kernel<<<800, 256>>>(node_idx, edge_idx);
    scan_two_kernel<<<2, 1024>>>();
    fill_kernel<<<800, 256>>>(node_idx, edge_idx);

    // segment reductions (no float atomics)
    reduce_v2e<<<N_EDGES, 64>>>(reinterpret_cast<const float4*>(x0),
                                reinterpret_cast<float4*>(x1));
    reduce_e2v<<<N_NODES, 64>>>(reinterpret_cast<const float4*>(x0),
                                reinterpret_cast<const float4*>(x1));

    // GEMM: out0 = g_m @ W^T + b
    {
        cudaFuncSetAttribute(gin_gemm_tf32,
                             cudaFuncAttributeMaxDynamicSharedMemorySize,
                             GEMM_SMEM_BYTES);
        int grid = (N_NODES + GBM - 1) / GBM;   // 782
        gin_gemm_tf32<<<grid, 256, GEMM_SMEM_BYTES>>>(W, b, out);
    }
}

// round 7
// speedup vs baseline: 1.4523x; 1.0684x over previous
#include <cuda_runtime.h>
#include <cstdint>

#define N_NODES 100000
#define N_NODES_PAD 100096   // padded so GEMM A-tile loads never go OOB
#define N_EDGES 50000
#define NNZ     800000
#define C       256
#define C4      (C / 4)   // 64 float4 per row

// ---------------- scratch (__device__ globals: allowed) ----------------
__device__ float    g_m[(size_t)N_NODES_PAD * C];  // tf32-encoded (x0 + m)
__device__ uint32_t g_w[(size_t)C * C];            // tf32-encoded W
__device__ int   d_cnt_e[N_EDGES];
__device__ int   d_cnt_n[N_NODES];
__device__ int   d_off_e[N_EDGES + 1];
__device__ int   d_off_n[N_NODES + 1];
__device__ int   d_memb_e[NNZ];                // node ids grouped by edge
__device__ int   d_memb_n[NNZ];                // edge ids grouped by node

__device__ __forceinline__ uint32_t f2tf32(float f) {
    uint32_t r;
    asm("cvt.rna.tf32.f32 %0, %1;" : "=r"(r) : "f"(f));
    return r;
}

// ---------------------------------------------------------------------------
// 0. convert W to tf32 bits (once per launch; cheap)
// ---------------------------------------------------------------------------
__global__ void convert_w_kernel(const float4* __restrict__ W) {
    int i = blockIdx.x * blockDim.x + threadIdx.x;   // 0 .. C*C/4-1
    float4 v = W[i];
    uint4 t;
    t.x = f2tf32(v.x); t.y = f2tf32(v.y); t.z = f2tf32(v.z); t.w = f2tf32(v.w);
    reinterpret_cast<uint4*>(g_w)[i] = t;
}

// ---------------------------------------------------------------------------
// 1. histogram of both index arrays (counters arrive zeroed: reduces zero them)
// ---------------------------------------------------------------------------
__global__ void hist_kernel(const int* __restrict__ node_idx,
                            const int* __restrict__ edge_idx) {
    int idx = blockIdx.x * blockDim.x + threadIdx.x;
    int stride = gridDim.x * blockDim.x;
    for (int i = idx; i < NNZ; i += stride) {
        atomicAdd(&d_cnt_e[edge_idx[i]], 1);
        atomicAdd(&d_cnt_n[node_idx[i]], 1);
    }
}

// ---------------------------------------------------------------------------
// 2. exclusive scan, VT=4 (int4). block 0 -> edges, block 1 -> nodes.
//    Re-zeroes counts (reused as rank counters by fill).
// ---------------------------------------------------------------------------
__global__ __launch_bounds__(1024)
void scan_two_kernel() {
    int* cnt;
    int* off;
    int  L;
    if (blockIdx.x == 0) { cnt = d_cnt_e; off = d_off_e; L = N_EDGES; }
    else                 { cnt = d_cnt_n; off = d_off_n; L = N_NODES; }

    const int tid  = threadIdx.x;
    const int lane = tid & 31;
    const int wid  = tid >> 5;
    __shared__ int warp_sum[32];

    const int L4 = L >> 2;
    int running = 0;
    for (int base4 = 0; base4 < L4; base4 += 1024) {
        int i4 = base4 + tid;
        int4 v = make_int4(0, 0, 0, 0);
        if (i4 < L4) v = reinterpret_cast<const int4*>(cnt)[i4];
        int p0 = v.x;
        int p1 = p0 + v.y;
        int p2 = p1 + v.z;
        int p3 = p2 + v.w;
        int tot = p3;
        int w = tot;
        #pragma unroll
        for (int d = 1; d < 32; d <<= 1) {
            int t = __shfl_up_sync(0xffffffffu, w, d);
            if (lane >= d) w += t;
        }
        if (lane == 31) warp_sum[wid] = w;
        __syncthreads();
        if (wid == 0) {
            int ws = warp_sum[lane];
            #pragma unroll
            for (int d = 1; d < 32; d <<= 1) {
                int t = __shfl_up_sync(0xffffffffu, ws, d);
                if (lane >= d) ws += t;
            }
            warp_sum[lane] = ws;
        }
        __syncthreads();
        int excl = (w - tot) + (wid > 0 ? warp_sum[wid - 1] : 0) + running;
        if (i4 < L4) {
            int i = i4 * 4;
            off[i + 1] = excl + p0;
            off[i + 2] = excl + p1;
            off[i + 3] = excl + p2;
            off[i + 4] = excl + p3;
        }
        running += warp_sum[31];
        __syncthreads();
    }
    if (tid == 0) off[0] = 0;
    for (int i = tid; i < L; i += 1024) cnt[i] = 0;
}

// ---------------------------------------------------------------------------
// 3. fill member lists (rank via int atomics)
// ---------------------------------------------------------------------------
__global__ void fill_kernel(const int* __restrict__ node_idx,
                            const int* __restrict__ edge_idx) {
    int idx = blockIdx.x * blockDim.x + threadIdx.x;
    int stride = gridDim.x * blockDim.x;
    for (int i = idx; i < NNZ; i += stride) {
        int n = node_idx[i];
        int e = edge_idx[i];
        int re = atomicAdd(&d_cnt_e[e], 1);
        d_memb_e[d_off_e[e] + re] = n;
        int rn = atomicAdd(&d_cnt_n[n], 1);
        d_memb_n[d_off_n[n] + rn] = e;
    }
}

// ---------------------------------------------------------------------------
// 4. reduce v2e: x1[e] = sum of x0 rows. Also zeroes d_cnt_e for next replay.
// ---------------------------------------------------------------------------
__global__ __launch_bounds__(64)
void reduce_v2e(const float4* __restrict__ x0, float4* __restrict__ x1) {
    const int e   = blockIdx.x;
    const int tid = threadIdx.x;
    int beg = d_off_e[e];
    int end = d_off_e[e + 1];
    if (tid == 0) d_cnt_e[e] = 0;

    float4 s0 = make_float4(0.f, 0.f, 0.f, 0.f);
    float4 s1 = make_float4(0.f, 0.f, 0.f, 0.f);
    int j = beg;
    for (; j + 1 < end; j += 2) {
        int n0 = __ldg(&d_memb_e[j]);
        int n1 = __ldg(&d_memb_e[j + 1]);
        float4 v0 = __ldg(&x0[(size_t)n0 * C4 + tid]);
        float4 v1 = __ldg(&x0[(size_t)n1 * C4 + tid]);
        s0.x += v0.x; s0.y += v0.y; s0.z += v0.z; s0.w += v0.w;
        s1.x += v1.x; s1.y += v1.y; s1.z += v1.z; s1.w += v1.w;
    }
    if (j < end) {
        int n0 = __ldg(&d_memb_e[j]);
        float4 v0 = __ldg(&x0[(size_t)n0 * C4 + tid]);
        s0.x += v0.x; s0.y += v0.y; s0.z += v0.z; s0.w += v0.w;
    }
    s0.x += s1.x; s0.y += s1.y; s0.z += s1.z; s0.w += s1.w;
    x1[(size_t)e * C4 + tid] = s0;
}

// ---------------------------------------------------------------------------
// 5. reduce e2v (+x0, tf32-encode): g_m[n] = tf32(x0[n] + sum x1[e]).
//    Also zeroes d_cnt_n for next replay.
// ---------------------------------------------------------------------------
__global__ __launch_bounds__(64)
void reduce_e2v(const float4* __restrict__ x0, const float4* __restrict__ x1) {
    const int n   = blockIdx.x;
    const int tid = threadIdx.x;
    int beg = d_off_n[n];
    int end = d_off_n[n + 1];
    if (tid == 0) d_cnt_n[n] = 0;

    float4 s0 = __ldg(&x0[(size_t)n * C4 + tid]);
    float4 s1 = make_float4(0.f, 0.f, 0.f, 0.f);
    int j = beg;
    for (; j + 1 < end; j += 2) {
        int e0 = __ldg(&d_memb_n[j]);
        int e1 = __ldg(&d_memb_n[j + 1]);
        float4 v0 = __ldg(&x1[(size_t)e0 * C4 + tid]);
        float4 v1 = __ldg(&x1[(size_t)e1 * C4 + tid]);
        s0.x += v0.x; s0.y += v0.y; s0.z += v0.z; s0.w += v0.w;
        s1.x += v1.x; s1.y += v1.y; s1.z += v1.z; s1.w += v1.w;
    }
    if (j < end) {
        int e0 = __ldg(&d_memb_n[j]);
        float4 v0 = __ldg(&x1[(size_t)e0 * C4 + tid]);
        s0.x += v0.x; s0.y += v0.y; s0.z += v0.z; s0.w += v0.w;
    }
    s0.x += s1.x; s0.y += s1.y; s0.z += s1.z; s0.w += s1.w;
    uint4 t;
    t.x = f2tf32(s0.x); t.y = f2tf32(s0.y); t.z = f2tf32(s0.z); t.w = f2tf32(s0.w);
    reinterpret_cast<uint4*>(g_m)[(size_t)n * C4 + tid] = t;
}

// ---------------------------------------------------------------------------
// 6. GEMM: out0 = g_m @ g_w^T + b — TF32 mma, BM=128 BN=256 GBK=16,
//    operands pre-converted, cp.async 2-stage pipeline.
// ---------------------------------------------------------------------------
#define GBM 128
#define GBK 16
#define SPAD 20
#define NTILES (C / GBK)

__device__ __forceinline__ void cp16(void* smem_dst, const void* gmem_src) {
    uint32_t s = (uint32_t)__cvta_generic_to_shared(smem_dst);
    asm volatile("cp.async.cg.shared.global [%0], [%1], 16;\n" :: "r"(s), "l"(gmem_src));
}
#define CP_COMMIT()   asm volatile("cp.async.commit_group;\n" ::: "memory")
#define CP_WAIT(n)    asm volatile("cp.async.wait_group %0;\n" :: "n"(n) : "memory")

__device__ __forceinline__ void mma_tf32_v(float c[4], const uint32_t a[4], const uint32_t b[2]) {
    asm volatile(
        "mma.sync.aligned.m16n8k8.row.col.f32.tf32.tf32.f32 "
        "{%0,%1,%2,%3}, {%4,%5,%6,%7}, {%8,%9}, {%0,%1,%2,%3};\n"
        : "+f"(c[0]), "+f"(c[1]), "+f"(c[2]), "+f"(c[3])
        : "r"(a[0]), "r"(a[1]), "r"(a[2]), "r"(a[3]), "r"(b[0]), "r"(b[1]));
}

__global__ __launch_bounds__(256, 1)
void gin_gemm_tf32(const float* __restrict__ bias,
                   float* __restrict__ out) {
    extern __shared__ uint32_t smem[];
    uint32_t* As0 = smem;                    // [2][GBM][SPAD]
    uint32_t* Bs0 = smem + 2 * GBM * SPAD;   // [2][256][SPAD]

    const int tid  = threadIdx.x;
    const int lane = tid & 31;
    const int wid  = tid >> 5;
    const int m_off = (wid >> 2) * 64;   // 0 or 64
    const int n_off = (wid & 3) * 64;    // 0,64,128,192
    const int m0 = blockIdx.x * GBM;

    // quad mappings (16B units)
    const int a_row0 = tid >> 2;               // quads 0..255: rows 0..63
    const int a_cq0  = (tid & 3) * 4;
    const int a_row1 = a_row0 + 64;            // quads 256..511: rows 64..127
    const uint32_t* gm = reinterpret_cast<const uint32_t*>(g_m);

    const int b_row0 = tid >> 2;               // 0..63
    const int b_cq0  = (tid & 3) * 4;

    float acc[4][8][4];
    #pragma unroll
    for (int mf = 0; mf < 4; mf++)
        #pragma unroll
        for (int nf = 0; nf < 8; nf++)
            #pragma unroll
            for (int q = 0; q < 4; q++)
                acc[mf][nf][q] = 0.f;

    const int r  = lane >> 2;
    const int cq = lane & 3;

    // ---- tile issue helper (A: 2 quads, B: 4 quads per thread) ----
    auto issue_tile = [&](int t, int buf) {
        const int k0 = t * GBK;
        uint32_t* A = As0 + buf * GBM * SPAD;
        uint32_t* B = Bs0 + buf * 256 * SPAD;
        cp16(&A[a_row0 * SPAD + a_cq0], &gm[(size_t)(m0 + a_row0) * C + k0 + a_cq0]);
        cp16(&A[a_row1 * SPAD + a_cq0], &gm[(size_t)(m0 + a_row1) * C + k0 + a_cq0]);
        #pragma unroll
        for (int s = 0; s < 4; s++) {
            int row = b_row0 + s * 64;
            cp16(&B[row * SPAD + b_cq0], &g_w[(size_t)row * C + k0 + b_cq0]);
        }
        CP_COMMIT();
    };

    issue_tile(0, 0);
    issue_tile(1, 1);
    CP_WAIT(1);
    __syncthreads();

    for (int t = 0; t < NTILES; t++) {
        const int buf = t & 1;
        uint32_t* A = As0 + buf * GBM * SPAD;
        uint32_t* B = Bs0 + buf * 256 * SPAD;

        // compute on current buffer: 2 ksteps of m16n8k8
        #pragma unroll
        for (int ks = 0; ks < 2; ks++) {
            const int kk = ks * 8;
            uint32_t aF[4][4];
            #pragma unroll
            for (int mf = 0; mf < 4; mf++) {
                int row = m_off + mf * 16 + r;
                aF[mf][0] = A[row * SPAD + kk + cq];
                aF[mf][1] = A[(row + 8) * SPAD + kk + cq];
                aF[mf][2] = A[row * SPAD + kk + cq + 4];
                aF[mf][3] = A[(row + 8) * SPAD + kk + cq + 4];
            }
            #pragma unroll
            for (int nf = 0; nf < 8; nf++) {
                uint32_t bF[2];
                int col = n_off + nf * 8 + r;
                bF[0] = B[col * SPAD + kk + cq];
                bF[1] = B[col * SPAD + kk + cq + 4];
                #pragma unroll
                for (int mf = 0; mf < 4; mf++)
                    mma_tf32_v(acc[mf][nf], aF[mf], bF);
            }
        }

        if (t + 2 < NTILES) {
            __syncthreads();               // all readers done with this buffer
            issue_tile(t + 2, buf);
            CP_WAIT(1);                    // tile t+1 landed
            __syncthreads();
        } else if (t + 1 < NTILES) {
            CP_WAIT(0);                    // last tile landed
            __syncthreads();
        }
    }

    // ---- epilogue ----
    #pragma unroll
    for (int mf = 0; mf < 4; mf++) {
        #pragma unroll
        for (int nf = 0; nf < 8; nf++) {
            int gc = n_off + nf * 8 + cq * 2;
            float bb0 = bias[gc];
            float bb1 = bias[gc + 1];
            int gr = m0 + m_off + mf * 16 + r;
            if (gr < N_NODES) {
                float2 v = make_float2(acc[mf][nf][0] + bb0, acc[mf][nf][1] + bb1);
                *reinterpret_cast<float2*>(&out[(size_t)gr * C + gc]) = v;
            }
            if (gr + 8 < N_NODES) {
                float2 v = make_float2(acc[mf][nf][2] + bb0, acc[mf][nf][3] + bb1);
                *reinterpret_cast<float2*>(&out[(size_t)(gr + 8) * C + gc]) = v;
            }
        }
    }
}

#define GEMM_SMEM_BYTES ((2 * GBM * SPAD + 2 * 256 * SPAD) * 4)

// ---------------------------------------------------------------------------
// Launch
// ---------------------------------------------------------------------------
extern "C" void kernel_launch(void* const* d_in, const int* in_sizes, int n_in,
                              void* d_out, int out_size) {
    const float* x0       = (const float*)d_in[0];
    const int*   node_idx = (const int*)d_in[1];
    const int*   edge_idx = (const int*)d_in[2];
    const float* W        = (const float*)d_in[3];
    const float* b        = (const float*)d_in[4];

    float* out = (float*)d_out;
    float* x1  = out + (size_t)N_NODES * C;

    // W -> tf32 (tiny)
    convert_w_kernel<<<C * C / 4 / 256, 256>>>(reinterpret_cast<const float4*>(W));

    // CSR build (counters pre-zeroed by previous replay's reduce kernels)
    hist_kernel<<<800, 256>>>(node_idx, edge_idx);
    scan_two_kernel<<<2, 1024>>>();
    fill_kernel<<<800, 256>>>(node_idx, edge_idx);

    // segment reductions (no float atomics)
    reduce_v2e<<<N_EDGES, 64>>>(reinterpret_cast<const float4*>(x0),
                                reinterpret_cast<float4*>(x1));
    reduce_e2v<<<N_NODES, 64>>>(reinterpret_cast<const float4*>(x0),
                                reinterpret_cast<const float4*>(x1));

    // GEMM: out0 = g_m @ g_w^T + b
    {
        cudaFuncSetAttribute(gin_gemm_tf32,
                             cudaFuncAttributeMaxDynamicSharedMemorySize,
                             GEMM_SMEM_BYTES);
        int grid = (N_NODES + GBM - 1) / GBM;   // 782
        gin_gemm_tf32<<<grid, 256, GEMM_SMEM_BYTES>>>(b, out);
    }
}

// round 8
// speedup vs baseline: 1.5045x; 1.0359x over previous
#include <cuda_runtime.h>
#include <cstdint>

#define N_NODES 100000
#define N_NODES_PAD 100096   // padded so GEMM A-tile loads never go OOB
#define N_EDGES 50000
#define NNZ     800000
#define C       256
#define C4      (C / 4)   // 64 float4 per row

// ---------------- scratch (__device__ globals: allowed) ----------------
__device__ float    g_m[(size_t)N_NODES_PAD * C];  // tf32-encoded (x0 + m)
__device__ uint32_t g_w[(size_t)C * C];            // tf32-encoded W
__device__ int   d_cnt_e[N_EDGES];
__device__ int   d_cnt_n[N_NODES];
__device__ int   d_off_e[N_EDGES + 1];
__device__ int   d_off_n[N_NODES + 1];
__device__ int   d_memb_e[NNZ];                // node ids grouped by edge
__device__ int   d_memb_n[NNZ];                // edge ids grouped by node

__device__ __forceinline__ uint32_t f2tf32(float f) {
    uint32_t r;
    asm("cvt.rna.tf32.f32 %0, %1;" : "=r"(r) : "f"(f));
    return r;
}

// ---------------------------------------------------------------------------
// 0. convert W to tf32 bits
// ---------------------------------------------------------------------------
__global__ void convert_w_kernel(const float4* __restrict__ W) {
    int i = blockIdx.x * blockDim.x + threadIdx.x;
    float4 v = W[i];
    uint4 t;
    t.x = f2tf32(v.x); t.y = f2tf32(v.y); t.z = f2tf32(v.z); t.w = f2tf32(v.w);
    reinterpret_cast<uint4*>(g_w)[i] = t;
}

// ---------------------------------------------------------------------------
// 1. histogram (counters arrive zeroed: reduce kernels zero them each replay)
// ---------------------------------------------------------------------------
__global__ void hist_kernel(const int* __restrict__ node_idx,
                            const int* __restrict__ edge_idx) {
    int idx = blockIdx.x * blockDim.x + threadIdx.x;
    int stride = gridDim.x * blockDim.x;
    for (int i = idx; i < NNZ; i += stride) {
        atomicAdd(&d_cnt_e[edge_idx[i]], 1);
        atomicAdd(&d_cnt_n[node_idx[i]], 1);
    }
}

// ---------------------------------------------------------------------------
// 2. exclusive scan, VT=4 (int4). block 0 -> edges, block 1 -> nodes.
// ---------------------------------------------------------------------------
__global__ __launch_bounds__(1024)
void scan_two_kernel() {
    int* cnt;
    int* off;
    int  L;
    if (blockIdx.x == 0) { cnt = d_cnt_e; off = d_off_e; L = N_EDGES; }
    else                 { cnt = d_cnt_n; off = d_off_n; L = N_NODES; }

    const int tid  = threadIdx.x;
    const int lane = tid & 31;
    const int wid  = tid >> 5;
    __shared__ int warp_sum[32];

    const int L4 = L >> 2;
    int running = 0;
    for (int base4 = 0; base4 < L4; base4 += 1024) {
        int i4 = base4 + tid;
        int4 v = make_int4(0, 0, 0, 0);
        if (i4 < L4) v = reinterpret_cast<const int4*>(cnt)[i4];
        int p0 = v.x;
        int p1 = p0 + v.y;
        int p2 = p1 + v.z;
        int p3 = p2 + v.w;
        int tot = p3;
        int w = tot;
        #pragma unroll
        for (int d = 1; d < 32; d <<= 1) {
            int t = __shfl_up_sync(0xffffffffu, w, d);
            if (lane >= d) w += t;
        }
        if (lane == 31) warp_sum[wid] = w;
        __syncthreads();
        if (wid == 0) {
            int ws = warp_sum[lane];
            #pragma unroll
            for (int d = 1; d < 32; d <<= 1) {
                int t = __shfl_up_sync(0xffffffffu, ws, d);
                if (lane >= d) ws += t;
            }
            warp_sum[lane] = ws;
        }
        __syncthreads();
        int excl = (w - tot) + (wid > 0 ? warp_sum[wid - 1] : 0) + running;
        if (i4 < L4) {
            int i = i4 * 4;
            off[i + 1] = excl + p0;
            off[i + 2] = excl + p1;
            off[i + 3] = excl + p2;
            off[i + 4] = excl + p3;
        }
        running += warp_sum[31];
        __syncthreads();
    }
    if (tid == 0) off[0] = 0;
    for (int i = tid; i < L; i += 1024) cnt[i] = 0;
}

// ---------------------------------------------------------------------------
// 3. fill member lists (rank via int atomics)
// ---------------------------------------------------------------------------
__global__ void fill_kernel(const int* __restrict__ node_idx,
                            const int* __restrict__ edge_idx) {
    int idx = blockIdx.x * blockDim.x + threadIdx.x;
    int stride = gridDim.x * blockDim.x;
    for (int i = idx; i < NNZ; i += stride) {
        int n = node_idx[i];
        int e = edge_idx[i];
        int re = atomicAdd(&d_cnt_e[e], 1);
        d_memb_e[d_off_e[e] + re] = n;
        int rn = atomicAdd(&d_cnt_n[n], 1);
        d_memb_n[d_off_n[n] + rn] = e;
    }
}

// ---------------------------------------------------------------------------
// 4. reduce v2e, channel-split: pass y covers float4 channels [y*32, y*32+32).
//    Block = 64 threads = 2 edges x 32 channels. Working set per pass = 51 MB
//    (half of x0) -> L2-resident. Zeroes d_cnt_e in pass 0.
// ---------------------------------------------------------------------------
__global__ __launch_bounds__(64)
void reduce_v2e_half(const float4* __restrict__ x0, float4* __restrict__ x1) {
    const int tid  = threadIdx.x;
    const int e    = blockIdx.x * 2 + (tid >> 5);
    const int lane = tid & 31;
    const int c4   = blockIdx.y * 32 + lane;
    if (blockIdx.y == 0 && lane == 0) d_cnt_e[e] = 0;

    int beg = __ldg(&d_off_e[e]);
    int end = __ldg(&d_off_e[e + 1]);

    float4 s0 = make_float4(0.f, 0.f, 0.f, 0.f);
    float4 s1 = make_float4(0.f, 0.f, 0.f, 0.f);
    int j = beg;
    for (; j + 1 < end; j += 2) {
        int n0 = __ldg(&d_memb_e[j]);
        int n1 = __ldg(&d_memb_e[j + 1]);
        float4 v0 = __ldg(&x0[(size_t)n0 * C4 + c4]);
        float4 v1 = __ldg(&x0[(size_t)n1 * C4 + c4]);
        s0.x += v0.x; s0.y += v0.y; s0.z += v0.z; s0.w += v0.w;
        s1.x += v1.x; s1.y += v1.y; s1.z += v1.z; s1.w += v1.w;
    }
    if (j < end) {
        int n0 = __ldg(&d_memb_e[j]);
        float4 v0 = __ldg(&x0[(size_t)n0 * C4 + c4]);
        s0.x += v0.x; s0.y += v0.y; s0.z += v0.z; s0.w += v0.w;
    }
    s0.x += s1.x; s0.y += s1.y; s0.z += s1.z; s0.w += s1.w;
    x1[(size_t)e * C4 + c4] = s0;
}

// ---------------------------------------------------------------------------
// 5. reduce e2v (+x0, tf32-encode): g_m[n] = tf32(x0[n] + sum x1[e]).
//    x1 (51 MB) is L2-resident; full-row blocks. Zeroes d_cnt_n.
// ---------------------------------------------------------------------------
__global__ __launch_bounds__(64)
void reduce_e2v(const float4* __restrict__ x0, const float4* __restrict__ x1) {
    const int n   = blockIdx.x;
    const int tid = threadIdx.x;
    int beg = d_off_n[n];
    int end = d_off_n[n + 1];
    if (tid == 0) d_cnt_n[n] = 0;

    float4 s0 = __ldg(&x0[(size_t)n * C4 + tid]);
    float4 s1 = make_float4(0.f, 0.f, 0.f, 0.f);
    int j = beg;
    for (; j + 1 < end; j += 2) {
        int e0 = __ldg(&d_memb_n[j]);
        int e1 = __ldg(&d_memb_n[j + 1]);
        float4 v0 = __ldg(&x1[(size_t)e0 * C4 + tid]);
        float4 v1 = __ldg(&x1[(size_t)e1 * C4 + tid]);
        s0.x += v0.x; s0.y += v0.y; s0.z += v0.z; s0.w += v0.w;
        s1.x += v1.x; s1.y += v1.y; s1.z += v1.z; s1.w += v1.w;
    }
    if (j < end) {
        int e0 = __ldg(&d_memb_n[j]);
        float4 v0 = __ldg(&x1[(size_t)e0 * C4 + tid]);
        s0.x += v0.x; s0.y += v0.y; s0.z += v0.z; s0.w += v0.w;
    }
    s0.x += s1.x; s0.y += s1.y; s0.z += s1.z; s0.w += s1.w;
    uint4 t;
    t.x = f2tf32(s0.x); t.y = f2tf32(s0.y); t.z = f2tf32(s0.z); t.w = f2tf32(s0.w);
    reinterpret_cast<uint4*>(g_m)[(size_t)n * C4 + tid] = t;
}

// ---------------------------------------------------------------------------
// 6. GEMM: out0 = g_m @ g_w^T + b — TF32 mma, BM=128 BN=256 GBK=16,
//    3-stage cp.async pipeline, ONE __syncthreads per k-tile.
// ---------------------------------------------------------------------------
#define GBM 128
#define GBK 16
#define SPAD 20
#define NTILES (C / GBK)
#define STAGES 3
#define A_WORDS (GBM * SPAD)
#define B_WORDS (256 * SPAD)

__device__ __forceinline__ void cp16(void* smem_dst, const void* gmem_src) {
    uint32_t s = (uint32_t)__cvta_generic_to_shared(smem_dst);
    asm volatile("cp.async.cg.shared.global [%0], [%1], 16;\n" :: "r"(s), "l"(gmem_src));
}
#define CP_COMMIT()   asm volatile("cp.async.commit_group;\n" ::: "memory")
#define CP_WAIT(n)    asm volatile("cp.async.wait_group %0;\n" :: "n"(n) : "memory")

__device__ __forceinline__ void mma_tf32_v(float c[4], const uint32_t a[4], const uint32_t b[2]) {
    asm volatile(
        "mma.sync.aligned.m16n8k8.row.col.f32.tf32.tf32.f32 "
        "{%0,%1,%2,%3}, {%4,%5,%6,%7}, {%8,%9}, {%0,%1,%2,%3};\n"
        : "+f"(c[0]), "+f"(c[1]), "+f"(c[2]), "+f"(c[3])
        : "r"(a[0]), "r"(a[1]), "r"(a[2]), "r"(a[3]), "r"(b[0]), "r"(b[1]));
}

__global__ __launch_bounds__(256, 1)
void gin_gemm_tf32(const float* __restrict__ bias,
                   float* __restrict__ out) {
    extern __shared__ uint32_t smem[];   // [STAGES][A_WORDS + B_WORDS]

    const int tid  = threadIdx.x;
    const int lane = tid & 31;
    const int wid  = tid >> 5;
    const int m_off = (wid >> 2) * 64;
    const int n_off = (wid & 3) * 64;
    const int m0 = blockIdx.x * GBM;

    // quad mappings (16B units)
    const int a_row0 = tid >> 2;
    const int a_cq0  = (tid & 3) * 4;
    const int a_row1 = a_row0 + 64;
    const uint32_t* gm = reinterpret_cast<const uint32_t*>(g_m);
    const int b_row0 = tid >> 2;
    const int b_cq0  = (tid & 3) * 4;

    float acc[4][8][4];
    #pragma unroll
    for (int mf = 0; mf < 4; mf++)
        #pragma unroll
        for (int nf = 0; nf < 8; nf++)
            #pragma unroll
            for (int q = 0; q < 4; q++)
                acc[mf][nf][q] = 0.f;

    const int r  = lane >> 2;
    const int cq = lane & 3;

    auto issue_tile = [&](int t, int buf) {
        const int k0 = t * GBK;
        uint32_t* A = smem + buf * (A_WORDS + B_WORDS);
        uint32_t* B = A + A_WORDS;
        cp16(&A[a_row0 * SPAD + a_cq0], &gm[(size_t)(m0 + a_row0) * C + k0 + a_cq0]);
        cp16(&A[a_row1 * SPAD + a_cq0], &gm[(size_t)(m0 + a_row1) * C + k0 + a_cq0]);
        #pragma unroll
        for (int s = 0; s < 4; s++) {
            int row = b_row0 + s * 64;
            cp16(&B[row * SPAD + b_cq0], &g_w[(size_t)row * C + k0 + b_cq0]);
        }
        CP_COMMIT();
    };

    issue_tile(0, 0);
    issue_tile(1, 1);

    #pragma unroll 1
    for (int t = 0; t < NTILES; t++) {
        if (t + 1 < NTILES) { CP_WAIT(1); } else { CP_WAIT(0); }
        __syncthreads();
        if (t + 2 < NTILES) issue_tile(t + 2, (t + 2) % STAGES);

        uint32_t* A = smem + (t % STAGES) * (A_WORDS + B_WORDS);
        uint32_t* B = A + A_WORDS;

        #pragma unroll
        for (int ks = 0; ks < 2; ks++) {
            const int kk = ks * 8;
            uint32_t aF[4][4];
            #pragma unroll
            for (int mf = 0; mf < 4; mf++) {
                int row = m_off + mf * 16 + r;
                aF[mf][0] = A[row * SPAD + kk + cq];
                aF[mf][1] = A[(row + 8) * SPAD + kk + cq];
                aF[mf][2] = A[row * SPAD + kk + cq + 4];
                aF[mf][3] = A[(row + 8) * SPAD + kk + cq + 4];
            }
            #pragma unroll
            for (int nf = 0; nf < 8; nf++) {
                uint32_t bF[2];
                int col = n_off + nf * 8 + r;
                bF[0] = B[col * SPAD + kk + cq];
                bF[1] = B[col * SPAD + kk + cq + 4];
                #pragma unroll
                for (int mf = 0; mf < 4; mf++)
                    mma_tf32_v(acc[mf][nf], aF[mf], bF);
            }
        }
    }

    // ---- epilogue ----
    #pragma unroll
    for (int mf = 0; mf < 4; mf++) {
        #pragma unroll
        for (int nf = 0; nf < 8; nf++) {
            int gc = n_off + nf * 8 + cq * 2;
            float bb0 = bias[gc];
            float bb1 = bias[gc + 1];
            int gr = m0 + m_off + mf * 16 + r;
            if (gr < N_NODES) {
                float2 v = make_float2(acc[mf][nf][0] + bb0, acc[mf][nf][1] + bb1);
                *reinterpret_cast<float2*>(&out[(size_t)gr * C + gc]) = v;
            }
            if (gr + 8 < N_NODES) {
                float2 v = make_float2(acc[mf][nf][2] + bb0, acc[mf][nf][3] + bb1);
                *reinterpret_cast<float2*>(&out[(size_t)(gr + 8) * C + gc]) = v;
            }
        }
    }
}

#define GEMM_SMEM_BYTES (STAGES * (A_WORDS + B_WORDS) * 4)

// ---------------------------------------------------------------------------
// Launch
// ---------------------------------------------------------------------------
extern "C" void kernel_launch(void* const* d_in, const int* in_sizes, int n_in,
                              void* d_out, int out_size) {
    const float* x0       = (const float*)d_in[0];
    const int*   node_idx = (const int*)d_in[1];
    const int*   edge_idx = (const int*)d_in[2];
    const float* W        = (const float*)d_in[3];
    const float* b        = (const float*)d_in[4];

    float* out = (float*)d_out;
    float* x1  = out + (size_t)N_NODES * C;

    // W -> tf32 (tiny)
    convert_w_kernel<<<C * C / 4 / 256, 256>>>(reinterpret_cast<const float4*>(W));

    // CSR build (counters pre-zeroed by previous replay's reduce kernels)
    hist_kernel<<<800, 256>>>(node_idx, edge_idx);
    scan_two_kernel<<<2, 1024>>>();
    fill_kernel<<<800, 256>>>(node_idx, edge_idx);

    // v2e: two channel-half passes (L2-resident working set per pass)
    {
        dim3 grid(N_EDGES / 2, 2);
        reduce_v2e_half<<<grid, 64>>>(reinterpret_cast<const float4*>(x0),
                                      reinterpret_cast<float4*>(x1));
    }

    // e2v (+x0, tf32 encode)
    reduce_e2v<<<N_NODES, 64>>>(reinterpret_cast<const float4*>(x0),
                                reinterpret_cast<const float4*>(x1));

    // GEMM: out0 = g_m @ g_w^T + b
    {
        cudaFuncSetAttribute(gin_gemm_tf32,
                             cudaFuncAttributeMaxDynamicSharedMemorySize,
                             GEMM_SMEM_BYTES);
        int grid = (N_NODES + GBM - 1) / GBM;
        gin_gemm_tf32<<<grid, 256, GEMM_SMEM_BYTES>>>(b, out);
    }
}